// round 5
// baseline (speedup 1.0000x reference)
#include <cuda_runtime.h>
#include <cuda_bf16.h>

// Problem constants
#define S_TOK 8192
#define D_DIM 2048
#define E_EXP 64
#define CAP   128
#define SEC   (S_TOK * E_EXP * CAP)   // 67108864
#define N4_ALL 33554432               // float4 count covering 134217728 floats
#define LAST_F 134217728              // final (tail) float index

// -------------------- device scratch --------------------
__device__ float g_gate[S_TOK];
__device__ int   g_expert[S_TOK];
__device__ int   g_loc[S_TOK];
__device__ int   g_off[S_TOK];
__device__ float g_me_part[(S_TOK / 64) * E_EXP];  // per-block column sums
__device__ int   g_cnt[E_EXP];
__device__ float g_laux;

// -------------------- host-side stream/events --------------------
struct GExec {
    cudaStream_t s2;
    cudaEvent_t  evFork, evJoin;
    GExec() {
        cudaStreamCreateWithFlags(&s2, cudaStreamNonBlocking);
        cudaEventCreateWithFlags(&evFork, cudaEventDisableTiming);
        cudaEventCreateWithFlags(&evJoin, cudaEventDisableTiming);
    }
};
static GExec g_exec;

// -------------------- packed fp32 FMA (FFMA2) --------------------
__device__ __forceinline__ void ffma2(float2& d, const float2& a, const float2& b) {
    unsigned long long dd = *(const unsigned long long*)&d;
    unsigned long long aa = *(const unsigned long long*)&a;
    unsigned long long bb = *(const unsigned long long*)&b;
    asm("fma.rn.f32x2 %0, %1, %2, %0;" : "+l"(dd) : "l"(aa), "l"(bb));
    d = *(float2*)&dd;
}

// -------------------- SM zero fill: tiny one-shot blocks (interleave-friendly)
// 65536 blocks x 256 threads x 2 float4 = 33554432 float4 = 536.8 MB.
// No grid-stride loop: short-lived blocks so the work distributor interleaves
// them with the gate pipeline's blocks instead of starving it.
__global__ __launch_bounds__(256) void k_zero(float4* __restrict__ out4,
                                              float* __restrict__ outf) {
    const float4 z = make_float4(0.f, 0.f, 0.f, 0.f);
    size_t i = (size_t)blockIdx.x * 512 + threadIdx.x;
    out4[i] = z;
    out4[i + 256] = z;
    if (blockIdx.x == 0 && threadIdx.x == 0) outf[LAST_F] = 0.0f;
}

// -------------------- GEMM + softmax + argmax --------------------
// BM=64 tokens/block, BN=64 experts, BK=32. 256 threads = 16x16.
#define ASTRIDE 36
__global__ __launch_bounds__(256) void k_gate(const float* __restrict__ x,
                                              const float* __restrict__ wg) {
    __shared__ float sm[2 * 64 * ASTRIDE];   // 4608 floats; reused as logits
    __shared__ float smax[64], sinv[64];
    float* sA = sm;
    float* sB = sm + 64 * ASTRIDE;

    const int tid = threadIdx.x;
    const int tx = tid & 15, ty = tid >> 4;
    const int m0 = blockIdx.x * 64;

    float2 acc[4][4];
#pragma unroll
    for (int i = 0; i < 4; i++)
#pragma unroll
        for (int j = 0; j < 4; j++) acc[i][j] = make_float2(0.f, 0.f);

    for (int k0 = 0; k0 < D_DIM; k0 += 32) {
        __syncthreads();
#pragma unroll
        for (int r = 0; r < 2; r++) {
            int q = tid + r * 256;
            int m = q >> 3, kq = q & 7;
            float4 vx = *(const float4*)(x + (size_t)(m0 + m) * D_DIM + k0 + kq * 4);
            *(float4*)&sA[m * ASTRIDE + kq * 4] = vx;
            float4 vw = *(const float4*)(wg + (size_t)m * D_DIM + k0 + kq * 4);
            *(float4*)&sB[m * ASTRIDE + kq * 4] = vw;
        }
        __syncthreads();

#pragma unroll
        for (int kk8 = 0; kk8 < 8; kk8++) {
            float4 a4[4], b4[4];
#pragma unroll
            for (int i = 0; i < 4; i++)
                a4[i] = *(const float4*)&sA[(ty + 16 * i) * ASTRIDE + kk8 * 4];
#pragma unroll
            for (int j = 0; j < 4; j++)
                b4[j] = *(const float4*)&sB[(tx + 16 * j) * ASTRIDE + kk8 * 4];
#pragma unroll
            for (int i = 0; i < 4; i++) {
                const float2* ap = (const float2*)&a4[i];
#pragma unroll
                for (int j = 0; j < 4; j++) {
                    const float2* bp = (const float2*)&b4[j];
                    ffma2(acc[i][j], ap[0], bp[0]);
                    ffma2(acc[i][j], ap[1], bp[1]);
                }
            }
        }
    }
    __syncthreads();

    float* logits = sm;   // [64][65]
#pragma unroll
    for (int i = 0; i < 4; i++)
#pragma unroll
        for (int j = 0; j < 4; j++)
            logits[(ty + 16 * i) * 65 + (tx + 16 * j)] = acc[i][j].x + acc[i][j].y;
    __syncthreads();

    if (tid < 64) {
        const float* row = &logits[tid * 65];
        float mx = row[0];
        int am = 0;
#pragma unroll 8
        for (int e = 1; e < 64; e++) {
            float v = row[e];
            if (v > mx) { mx = v; am = e; }
        }
        float sum = 0.f;
#pragma unroll 8
        for (int e = 0; e < 64; e++) sum += expf(row[e] - mx);
        float gate = 1.0f / sum;
        g_gate[m0 + tid] = gate;
        g_expert[m0 + tid] = am;
        smax[tid] = mx;
        sinv[tid] = gate;
    }
    __syncthreads();

    if (tid < 64) {
        float cs = 0.f;
#pragma unroll 8
        for (int t = 0; t < 64; t++)
            cs += expf(logits[t * 65 + tid] - smax[t]) * sinv[t];
        g_me_part[blockIdx.x * 64 + tid] = cs;
    }
}

// -------------------- ordered per-expert prefix scan --------------------
__global__ __launch_bounds__(256) void k_scan() {
    const int e = blockIdx.x;
    const int tid = threadIdx.x;
    __shared__ int ws[8];
    __shared__ int stot;
    int carry = 0;
    for (int it = 0; it < S_TOK / 256; it++) {
        int s = it * 256 + tid;
        int ind = (g_expert[s] == e);
        unsigned bal = __ballot_sync(0xffffffffu, ind);
        int lane = tid & 31, w = tid >> 5;
        int pre = __popc(bal & ((1u << lane) - 1u));
        if (lane == 0) ws[w] = __popc(bal);
        __syncthreads();
        if (tid == 0) {
            int a = 0;
#pragma unroll
            for (int i = 0; i < 8; i++) { int t = ws[i]; ws[i] = a; a += t; }
            stot = a;
        }
        __syncthreads();
        if (ind) g_loc[s] = carry + ws[w] + pre;
        carry += stot;
        __syncthreads();
    }
    if (tid == 0) g_cnt[e] = carry;
}

// -------------------- offsets + l_aux --------------------
__global__ __launch_bounds__(256) void k_meta() {
    int s = blockIdx.x * 256 + threadIdx.x;
    if (s < S_TOK) {
        int e = g_expert[s], loc = g_loc[s];
        g_off[s] = (loc < CAP) ? (s * (E_EXP * CAP) + e * CAP + loc) : -1;
    }
    if (blockIdx.x == 0 && threadIdx.x < 64) {
        __shared__ float red[2];
        float me = 0.f;
#pragma unroll 8
        for (int b = 0; b < S_TOK / 64; b++)
            me += g_me_part[b * 64 + threadIdx.x];
        float v = me * (float)g_cnt[threadIdx.x];
#pragma unroll
        for (int o = 16; o; o >>= 1) v += __shfl_down_sync(0xffffffffu, v, o);
        if ((threadIdx.x & 31) == 0) red[threadIdx.x >> 5] = v;
        __syncthreads();
        if (threadIdx.x == 0)
            g_laux = (red[0] + red[1]) * (64.0f / (8192.0f * 8192.0f));
    }
}

// -------------------- sparse scatter of nonzeros --------------------
__global__ __launch_bounds__(256) void k_scatter(float* __restrict__ out) {
    int s = blockIdx.x * 256 + threadIdx.x;
    if (s == 0) out[0] = g_laux;
    if (s < S_TOK) {
        int off = g_off[s];
        if (off >= 0) {
            out[1 + (size_t)off] = g_gate[s];
            out[1 + (size_t)SEC + (size_t)off] = 1.0f;
        }
    }
}

// -------------------- launch --------------------
extern "C" void kernel_launch(void* const* d_in, const int* in_sizes, int n_in,
                              void* d_out, int out_size) {
    const float* x  = (const float*)d_in[0];
    const float* wg = (const float*)d_in[1];
    float* out = (float*)d_out;

    // Fork: SM zero-fill of the entire output on a side stream, as 65536
    // tiny one-shot blocks that interleave with the gate pipeline's blocks.
    cudaEventRecord(g_exec.evFork, 0);
    cudaStreamWaitEvent(g_exec.s2, g_exec.evFork, 0);
    k_zero<<<65536, 256, 0, g_exec.s2>>>((float4*)out, out);
    cudaEventRecord(g_exec.evJoin, g_exec.s2);

    // Gate pipeline on the main stream, concurrent with the zero fill.
    k_gate<<<S_TOK / 64, 256>>>(x, wg);
    k_scan<<<E_EXP, 256>>>();
    k_meta<<<S_TOK / 256, 256>>>();

    // Join, then scatter the 16385 nonzeros.
    cudaStreamWaitEvent(0, g_exec.evJoin, 0);
    k_scatter<<<S_TOK / 256, 256>>>(out);
}

// round 6
// speedup vs baseline: 1.4348x; 1.4348x over previous
#include <cuda_runtime.h>
#include <cuda_bf16.h>

// Problem constants
#define S_TOK 8192
#define D_DIM 2048
#define E_EXP 64
#define CAP   128
#define SEC   (S_TOK * E_EXP * CAP)   // 67108864
#define LAST_F 134217728              // final (tail) float index; out_size = LAST_F+1

// -------------------- device scratch --------------------
__device__ float g_gate[S_TOK];
__device__ int   g_expert[S_TOK];
__device__ int   g_loc[S_TOK];
__device__ float g_me_part[(S_TOK / 64) * E_EXP];  // per-block column sums
__device__ int   g_cnt[E_EXP];

// -------------------- packed fp32 FMA (FFMA2) --------------------
__device__ __forceinline__ void ffma2(float2& d, const float2& a, const float2& b) {
    unsigned long long dd = *(const unsigned long long*)&d;
    unsigned long long aa = *(const unsigned long long*)&a;
    unsigned long long bb = *(const unsigned long long*)&b;
    asm("fma.rn.f32x2 %0, %1, %2, %0;" : "+l"(dd) : "l"(aa), "l"(bb));
    d = *(float2*)&dd;
}

// -------------------- SM zero fill: 1 float4 per thread, one-shot blocks ----
// Measured 7.0 TB/s (LTS cap) in round 4 with this exact shape.
__global__ __launch_bounds__(256) void k_zero(float4* __restrict__ out4,
                                              float* __restrict__ outf) {
    unsigned i = blockIdx.x * 256u + threadIdx.x;
    out4[i] = make_float4(0.f, 0.f, 0.f, 0.f);
    if (i == 0) outf[LAST_F] = 0.0f;
}

// -------------------- GEMM + softmax + argmax --------------------
// BM=64 tokens/block, BN=64 experts, BK=32. 256 threads = 16x16.
#define ASTRIDE 36
__global__ __launch_bounds__(256) void k_gate(const float* __restrict__ x,
                                              const float* __restrict__ wg) {
    __shared__ float sm[2 * 64 * ASTRIDE];   // 4608 floats; reused as logits
    __shared__ float smax[64], sinv[64];
    float* sA = sm;
    float* sB = sm + 64 * ASTRIDE;

    const int tid = threadIdx.x;
    const int tx = tid & 15, ty = tid >> 4;
    const int m0 = blockIdx.x * 64;

    float2 acc[4][4];
#pragma unroll
    for (int i = 0; i < 4; i++)
#pragma unroll
        for (int j = 0; j < 4; j++) acc[i][j] = make_float2(0.f, 0.f);

    for (int k0 = 0; k0 < D_DIM; k0 += 32) {
        __syncthreads();
#pragma unroll
        for (int r = 0; r < 2; r++) {
            int q = tid + r * 256;
            int m = q >> 3, kq = q & 7;
            float4 vx = *(const float4*)(x + (size_t)(m0 + m) * D_DIM + k0 + kq * 4);
            *(float4*)&sA[m * ASTRIDE + kq * 4] = vx;
            float4 vw = *(const float4*)(wg + (size_t)m * D_DIM + k0 + kq * 4);
            *(float4*)&sB[m * ASTRIDE + kq * 4] = vw;
        }
        __syncthreads();

#pragma unroll
        for (int kk8 = 0; kk8 < 8; kk8++) {
            float4 a4[4], b4[4];
#pragma unroll
            for (int i = 0; i < 4; i++)
                a4[i] = *(const float4*)&sA[(ty + 16 * i) * ASTRIDE + kk8 * 4];
#pragma unroll
            for (int j = 0; j < 4; j++)
                b4[j] = *(const float4*)&sB[(tx + 16 * j) * ASTRIDE + kk8 * 4];
#pragma unroll
            for (int i = 0; i < 4; i++) {
                const float2* ap = (const float2*)&a4[i];
#pragma unroll
                for (int j = 0; j < 4; j++) {
                    const float2* bp = (const float2*)&b4[j];
                    ffma2(acc[i][j], ap[0], bp[0]);
                    ffma2(acc[i][j], ap[1], bp[1]);
                }
            }
        }
    }
    __syncthreads();

    float* logits = sm;   // [64][65]
#pragma unroll
    for (int i = 0; i < 4; i++)
#pragma unroll
        for (int j = 0; j < 4; j++)
            logits[(ty + 16 * i) * 65 + (tx + 16 * j)] = acc[i][j].x + acc[i][j].y;
    __syncthreads();

    if (tid < 64) {
        const float* row = &logits[tid * 65];
        float mx = row[0];
        int am = 0;
#pragma unroll 8
        for (int e = 1; e < 64; e++) {
            float v = row[e];
            if (v > mx) { mx = v; am = e; }
        }
        float sum = 0.f;
#pragma unroll 8
        for (int e = 0; e < 64; e++) sum += expf(row[e] - mx);
        float gate = 1.0f / sum;
        g_gate[m0 + tid] = gate;
        g_expert[m0 + tid] = am;
        smax[tid] = mx;
        sinv[tid] = gate;
    }
    __syncthreads();

    if (tid < 64) {
        float cs = 0.f;
#pragma unroll 8
        for (int t = 0; t < 64; t++)
            cs += expf(logits[t * 65 + tid] - smax[t]) * sinv[t];
        g_me_part[blockIdx.x * 64 + tid] = cs;
    }
}

// -------------------- ordered per-expert prefix scan --------------------
__global__ __launch_bounds__(256) void k_scan() {
    const int e = blockIdx.x;
    const int tid = threadIdx.x;
    __shared__ int ws[8];
    __shared__ int stot;
    int carry = 0;
    for (int it = 0; it < S_TOK / 256; it++) {
        int s = it * 256 + tid;
        int ind = (g_expert[s] == e);
        unsigned bal = __ballot_sync(0xffffffffu, ind);
        int lane = tid & 31, w = tid >> 5;
        int pre = __popc(bal & ((1u << lane) - 1u));
        if (lane == 0) ws[w] = __popc(bal);
        __syncthreads();
        if (tid == 0) {
            int a = 0;
#pragma unroll
            for (int i = 0; i < 8; i++) { int t = ws[i]; ws[i] = a; a += t; }
            stot = a;
        }
        __syncthreads();
        if (ind) g_loc[s] = carry + ws[w] + pre;
        carry += stot;
        __syncthreads();
    }
    if (tid == 0) g_cnt[e] = carry;
}

// -------------------- offsets + l_aux + sparse scatter (fused) --------------
__global__ __launch_bounds__(256) void k_meta(float* __restrict__ out) {
    int s = blockIdx.x * 256 + threadIdx.x;
    if (s < S_TOK) {
        int e = g_expert[s], loc = g_loc[s];
        if (loc < CAP) {
            size_t off = (size_t)s * (E_EXP * CAP) + e * CAP + loc;
            out[1 + off] = g_gate[s];
            out[1 + (size_t)SEC + off] = 1.0f;
        }
    }
    if (blockIdx.x == 0 && threadIdx.x < 64) {
        __shared__ float red[2];
        float me = 0.f;
#pragma unroll 8
        for (int b = 0; b < S_TOK / 64; b++)
            me += g_me_part[b * 64 + threadIdx.x];
        float v = me * (float)g_cnt[threadIdx.x];
#pragma unroll
        for (int o = 16; o; o >>= 1) v += __shfl_down_sync(0xffffffffu, v, o);
        if ((threadIdx.x & 31) == 0) red[threadIdx.x >> 5] = v;
        __syncthreads();
        if (threadIdx.x == 0)
            out[0] = (red[0] + red[1]) * (64.0f / (8192.0f * 8192.0f));
    }
}

// -------------------- launch (strictly serial, single stream) ---------------
extern "C" void kernel_launch(void* const* d_in, const int* in_sizes, int n_in,
                              void* d_out, int out_size) {
    const float* x  = (const float*)d_in[0];
    const float* wg = (const float*)d_in[1];
    float* out = (float*)d_out;

    // 1) Bulk zero of the whole output at SM store bandwidth (~7 TB/s shape).
    k_zero<<<LAST_F / 1024, 256>>>((float4*)out, out);
    // 2) Gate GEMM + softmax/argmax.
    k_gate<<<S_TOK / 64, 256>>>(x, wg);
    // 3) Per-expert ordered positions.
    k_scan<<<E_EXP, 256>>>();
    // 4) l_aux + scatter of the 16385 nonzeros.
    k_meta<<<S_TOK / 256, 256>>>(out);
}